// round 13
// baseline (speedup 1.0000x reference)
#include <cuda_runtime.h>
#include <cstdint>

#define BB 1024
#define LL 400
#define TMM 150
#define EPSF 1e-5f

// ---------------- scratch (device globals; no allocations allowed) ----------
__device__ float g_xa[(size_t)BB * 3 * LL];        // [B,3,400]
__device__ float g_m0[(size_t)BB * TMM * 3];       // [B,150,3]
__device__ float g_s0[(size_t)BB * LL * 3];        // [B,400,3]
__device__ float g_a0[(size_t)BB * LL * 3];        // [B,400,3]

// ---------------- helpers ---------------------------------------------------
__device__ __forceinline__ float tanh_(float x) {
    float y;
    asm("tanh.approx.f32 %0, %1;" : "=f"(y) : "f"(x));
    return y;
}
__device__ __forceinline__ float sigm_(float x) {
    return fmaf(0.5f, tanh_(0.5f * x), 0.5f);
}

// ---------------- conv1d + BN(eval) + LeakyReLU -----------------------------
__global__ void k_conv(const float* __restrict__ x,
                       const float* __restrict__ cw, const float* __restrict__ cb,
                       const float* __restrict__ bw, const float* __restrict__ bb,
                       const float* __restrict__ bm, const float* __restrict__ bv) {
    int idx = blockIdx.x * blockDim.x + threadIdx.x;
    if (idx >= BB * LL) return;
    int b = idx / LL, t = idx % LL;
    const float* xb = x + (size_t)b * 3 * LL;
    float in[3][3];
#pragma unroll
    for (int ci = 0; ci < 3; ci++)
#pragma unroll
        for (int k = 0; k < 3; k++) {
            int tt = t + k - 1;
            in[ci][k] = (tt >= 0 && tt < LL) ? xb[ci * LL + tt] : 0.0f;
        }
#pragma unroll
    for (int co = 0; co < 3; co++) {
        float acc = cb[co];
#pragma unroll
        for (int ci = 0; ci < 3; ci++)
#pragma unroll
            for (int k = 0; k < 3; k++)
                acc = fmaf(cw[(co * 3 + ci) * 3 + k], in[ci][k], acc);
        float sc = bw[co] * rsqrtf(bv[co] + EPSF);
        acc = fmaf(acc - bm[co], sc, bb[co]);
        acc = (acc >= 0.0f) ? acc : 0.01f * acc;
        g_xa[((size_t)b * 3 + co) * LL + t] = acc;
    }
}

// ---------------- forward matmul SIDE: thread owns 4 columns (float4) -------
// out[b,t,c] = sum_k xa[b,c,k]*S[b,k,t], T=400. Row stride 1600B (16B-aligned).
__global__ void k_mm_fwd_s(const float* __restrict__ S, float* __restrict__ out) {
    int b = blockIdx.x;
    __shared__ float sxa[3][LL];
    for (int i = threadIdx.x; i < 3 * LL; i += blockDim.x)
        sxa[i / LL][i % LL] = g_xa[(size_t)b * 3 * LL + i];
    __syncthreads();
    int tg = threadIdx.x;           // 0..99 column groups of 4
    if (tg >= LL / 4) return;
    const float4* Sr = reinterpret_cast<const float4*>(S + (size_t)b * LL * LL) + tg;
    float a[3][4];
#pragma unroll
    for (int c = 0; c < 3; c++)
#pragma unroll
        for (int d = 0; d < 4; d++) a[c][d] = 0.f;
#pragma unroll 4
    for (int k = 0; k < LL; k++) {
        float4 v = Sr[(size_t)k * (LL / 4)];
#pragma unroll
        for (int c = 0; c < 3; c++) {
            float w = sxa[c][k];
            a[c][0] = fmaf(w, v.x, a[c][0]);
            a[c][1] = fmaf(w, v.y, a[c][1]);
            a[c][2] = fmaf(w, v.z, a[c][2]);
            a[c][3] = fmaf(w, v.w, a[c][3]);
        }
    }
    float* o = out + ((size_t)b * LL + 4 * tg) * 3;   // 12 contiguous floats
#pragma unroll
    for (int d = 0; d < 4; d++)
#pragma unroll
        for (int c = 0; c < 3; c++)
            o[d * 3 + c] = a[c][d];
}

// ---------------- forward matmul MAIN: thread owns 2 columns (float2) -------
// out[b,t,c] = sum_k xa[b,c,k]*M[b,k,t], T=150. Row stride 600B (8B-aligned).
__global__ void k_mm_fwd_m(const float* __restrict__ M, float* __restrict__ out) {
    int b = blockIdx.x;
    __shared__ float sxa[3][LL];
    for (int i = threadIdx.x; i < 3 * LL; i += blockDim.x)
        sxa[i / LL][i % LL] = g_xa[(size_t)b * 3 * LL + i];
    __syncthreads();
    int tg = threadIdx.x;           // 0..74 column groups of 2
    if (tg >= TMM / 2) return;
    const float2* Mr = reinterpret_cast<const float2*>(M + (size_t)b * LL * TMM) + tg;
    float a[3][2];
#pragma unroll
    for (int c = 0; c < 3; c++) { a[c][0] = 0.f; a[c][1] = 0.f; }
#pragma unroll 8
    for (int k = 0; k < LL; k++) {
        float2 v = Mr[(size_t)k * (TMM / 2)];
#pragma unroll
        for (int c = 0; c < 3; c++) {
            float w = sxa[c][k];
            a[c][0] = fmaf(w, v.x, a[c][0]);
            a[c][1] = fmaf(w, v.y, a[c][1]);
        }
    }
    float* o = out + ((size_t)b * TMM + 2 * tg) * 3;  // 6 contiguous floats
#pragma unroll
    for (int d = 0; d < 2; d++)
#pragma unroll
        for (int c = 0; c < 3; c++)
            o[d * 3 + c] = a[c][d];
}

// ---------------- fused transpose matmul, 8-LANE-GROUP per row --------------
__global__ void k_mm_bwd(const float* __restrict__ xm,   // [B,3,150]
                         const float* __restrict__ xs,   // [B,3,400]
                         const float* __restrict__ M,    // [B,400,150]
                         const float* __restrict__ S) {  // [B,400,400]
    int b = blockIdx.x;
    __shared__ float sm_[3 * 152];
    __shared__ float ss_[3 * LL];
    const float* xmB = xm + (size_t)b * 3 * TMM;
    const float* xsB = xs + (size_t)b * 3 * LL;
    for (int i = threadIdx.x; i < 3 * TMM; i += blockDim.x)
        sm_[(i / TMM) * 152 + (i % TMM)] = xmB[i];
    for (int i = threadIdx.x; i < 3 * LL; i += blockDim.x)
        ss_[i] = xsB[i];
    __syncthreads();

    int warp = threadIdx.x >> 5, lane = threadIdx.x & 31;
    int grp = lane >> 3;          // 0..3  (row within warp-pass)
    int gl  = lane & 7;           // 0..7  (lane within group)
    int nWarps = blockDim.x >> 5;
    int rowsPerPass = nWarps * 4;

    for (int t0 = warp * 4 + grp; t0 < LL + 3; t0 += rowsPerPass) {
        bool valid = (t0 < LL);
        int t = valid ? t0 : (LL - 1);

        float a0 = 0.f, a1 = 0.f, a2 = 0.f;

        const float4* Sr = reinterpret_cast<const float4*>(S + ((size_t)b * LL + t) * LL);
        for (int k4 = gl; k4 < LL / 4; k4 += 8) {
            float4 v = Sr[k4];
            int k0 = 4 * k4;
            a0 = fmaf(ss_[k0], v.x, fmaf(ss_[k0 + 1], v.y, fmaf(ss_[k0 + 2], v.z, fmaf(ss_[k0 + 3], v.w, a0))));
            a1 = fmaf(ss_[LL + k0], v.x, fmaf(ss_[LL + k0 + 1], v.y, fmaf(ss_[LL + k0 + 2], v.z, fmaf(ss_[LL + k0 + 3], v.w, a1))));
            a2 = fmaf(ss_[2 * LL + k0], v.x, fmaf(ss_[2 * LL + k0 + 1], v.y, fmaf(ss_[2 * LL + k0 + 2], v.z, fmaf(ss_[2 * LL + k0 + 3], v.w, a2))));
        }

        const float2* Mr = reinterpret_cast<const float2*>(M + ((size_t)b * LL + t) * TMM);
        for (int j2 = gl; j2 < TMM / 2; j2 += 8) {
            float2 v = Mr[j2];
            int j0 = 2 * j2;
            a0 = fmaf(sm_[j0], v.x, fmaf(sm_[j0 + 1], v.y, a0));
            a1 = fmaf(sm_[152 + j0], v.x, fmaf(sm_[152 + j0 + 1], v.y, a1));
            a2 = fmaf(sm_[304 + j0], v.x, fmaf(sm_[304 + j0 + 1], v.y, a2));
        }

#pragma unroll
        for (int o = 4; o; o >>= 1) {
            a0 += __shfl_xor_sync(0xffffffffu, a0, o);
            a1 += __shfl_xor_sync(0xffffffffu, a1, o);
            a2 += __shfl_xor_sync(0xffffffffu, a2, o);
        }
        if (gl == 0 && valid) {
            float* o = g_a0 + ((size_t)b * LL + t) * 3;
            o[0] = a0; o[1] = a1; o[2] = a2;
        }
    }
}

// ---------------- fused 2-layer LSTM + LayerNorm, SMEM-resident -------------
#define SEQW 5
__global__ void __launch_bounds__(32)
k_lstm_ln(const float* __restrict__ Wih0, const float* __restrict__ Whh0,
          const float* __restrict__ bih0, const float* __restrict__ bhh0,
          const float* __restrict__ lnw0, const float* __restrict__ lnb0,
          const float* __restrict__ in0, float* __restrict__ out0,
          int T0, int nB0, int nW0,
          const float* __restrict__ Wih1, const float* __restrict__ Whh1,
          const float* __restrict__ bih1, const float* __restrict__ bhh1,
          const float* __restrict__ lnw1, const float* __restrict__ lnb1,
          const float* __restrict__ in1, float* __restrict__ out1,
          int T1, int nB1) {
    __shared__ float sxin[SEQW * (3 * LL + 5)];   // 6025 words
    __shared__ float shout[SEQW * (3 * LL + 5)];  // 6025 words
    int warpId = blockIdx.x;
    int lane = threadIdx.x & 31;

    bool first = (warpId < nW0);
    const float* Wih = first ? Wih0 : Wih1;
    const float* Whh = first ? Whh0 : Whh1;
    const float* bih = first ? bih0 : bih1;
    const float* bhh = first ? bhh0 : bhh1;
    const float* lnw = first ? lnw0 : lnw1;
    const float* lnb = first ? lnb0 : lnb1;
    const float* inp = first ? in0 : in1;
    float* outp = first ? out0 : out1;
    int T  = first ? T0 : T1;
    int nB = first ? nB0 : nB1;
    int widx = first ? warpId : (warpId - nW0);

    int T3 = 3 * T;
    int stride = T3 + 5;                 // odd -> coprime with 32 banks
    int b0 = widx * SEQW;
    int nv = nB - b0; if (nv > SEQW) nv = SEQW;

    // ---- stage inputs into SMEM (coalesced) ----
    const float* src = inp + (size_t)b0 * T3;
    for (int s = 0; s < nv; s++)
        for (int i = lane; i < T3; i += 32)
            sxin[s * stride + i] = src[s * T3 + i];
    __syncwarp();

    // ---- lane mapping: 5 triples, lanes 15-31 shadow triple 4 ----
    int ln_ = (lane < 3 * SEQW) ? lane : (3 * SEQW - 1);
    int triple = ln_ / 3;
    int u = ln_ - triple * 3;
    int base = triple * 3;
    const float* xin = sxin + triple * stride;
    float* hout = shout + triple * stride;

    // ---- per-lane weights: gates (i,f,g,o) of unit u, layers 0/1 ----
    float wi1[4][3], wh1[4][3], b1[4], wi2[4][3], wh2[4][3], b2[4];
#pragma unroll
    for (int q = 0; q < 4; q++) {
        int gi = q * 3 + u;
#pragma unroll
        for (int v = 0; v < 3; v++) {
            wi1[q][v] = Wih[gi * 3 + v];
            wh1[q][v] = Whh[gi * 3 + v];
            wi2[q][v] = Wih[36 + gi * 3 + v];
            wh2[q][v] = Whh[36 + gi * 3 + v];
        }
        b1[q] = bih[gi] + bhh[gi];
        b2[q] = bih[12 + gi] + bhh[12 + gi];
    }

    // ---- recurrence (SMEM in -> SMEM out, zero aliasing) ----
    float c1 = 0.f, c2 = 0.f;
    float h1a = 0.f, h1b = 0.f, h1c = 0.f;
    float h2a = 0.f, h2b = 0.f, h2c = 0.f;

    float nx0 = xin[0], nx1 = xin[1], nx2 = xin[2];
    float xc[4];
#pragma unroll
    for (int q = 0; q < 4; q++)
        xc[q] = fmaf(nx0, wi1[q][0], fmaf(nx1, wi1[q][1], fmaf(nx2, wi1[q][2], b1[q])));

    for (int t = 0; t < T; t++) {
        int tn3 = ((t + 1 < T) ? (t + 1) : t) * 3;
        nx0 = xin[tn3]; nx1 = xin[tn3 + 1]; nx2 = xin[tn3 + 2];

        // layer-2 recurrent part (off the h1 chain)
        float p2[4];
#pragma unroll
        for (int q = 0; q < 4; q++)
            p2[q] = fmaf(h2a, wh2[q][0], fmaf(h2b, wh2[q][1], fmaf(h2c, wh2[q][2], b2[q])));

        // ---- layer 1 (on-chain: 3 FMA after h1 shfl) ----
        float g[4];
#pragma unroll
        for (int q = 0; q < 4; q++)
            g[q] = fmaf(h1a, wh1[q][0], fmaf(h1b, wh1[q][1], fmaf(h1c, wh1[q][2], xc[q])));
        float si = sigm_(g[0]), sf = sigm_(g[1]), tg = tanh_(g[2]), so = sigm_(g[3]);
        c1 = fmaf(sf, c1, si * tg);
        float h1u = so * tanh_(c1);
        h1a = __shfl_sync(0xffffffffu, h1u, base);
        h1b = __shfl_sync(0xffffffffu, h1u, base + 1);
        h1c = __shfl_sync(0xffffffffu, h1u, base + 2);

        // next step's x contribution (off-chain)
#pragma unroll
        for (int q = 0; q < 4; q++)
            xc[q] = fmaf(nx0, wi1[q][0], fmaf(nx1, wi1[q][1], fmaf(nx2, wi1[q][2], b1[q])));

        // ---- layer 2 (on-chain: 3 FMA after h1) ----
#pragma unroll
        for (int q = 0; q < 4; q++)
            g[q] = fmaf(h1a, wi2[q][0], fmaf(h1b, wi2[q][1], fmaf(h1c, wi2[q][2], p2[q])));
        float si2 = sigm_(g[0]), sf2 = sigm_(g[1]), tg2 = tanh_(g[2]), so2 = sigm_(g[3]);
        c2 = fmaf(sf2, c2, si2 * tg2);
        float h2u = so2 * tanh_(c2);
        h2a = __shfl_sync(0xffffffffu, h2u, base);
        h2b = __shfl_sync(0xffffffffu, h2u, base + 1);
        h2c = __shfl_sync(0xffffffffu, h2u, base + 2);

        hout[3 * t + u] = h2u;   // write-only buffer (shadow lanes dup lane 14)
    }
    __syncwarp();

    // ---- LayerNorm over (T,3) per sequence, write transposed [3,T] ----
    float s1 = 0.f, s2 = 0.f;
    for (int t = 0; t < T; t++) {
        float v = hout[3 * t + u];
        s1 += v;
        s2 = fmaf(v, v, s2);
    }
    float sa = __shfl_sync(0xffffffffu, s1, base) +
               __shfl_sync(0xffffffffu, s1, base + 1) +
               __shfl_sync(0xffffffffu, s1, base + 2);
    float sq = __shfl_sync(0xffffffffu, s2, base) +
               __shfl_sync(0xffffffffu, s2, base + 1) +
               __shfl_sync(0xffffffffu, s2, base + 2);
    float invn = 1.0f / (float)T3;
    float mu = sa * invn;
    float var = sq * invn - mu * mu;
    float rs = rsqrtf(var + EPSF);

    int b = b0 + triple;
    bool ok = (lane < 3 * SEQW) && (b < nB);
    if (ok) {
        float* op = outp + (size_t)b * T3 + u * T;   // [B,3,T], row u
        for (int t2 = 0; t2 < T / 2; t2++) {
            int t = 2 * t2;
            int i0 = 3 * t + u, i1 = 3 * t + 3 + u;
            float2 v;
            v.x = fmaf((hout[i0] - mu) * rs, lnw[i0], lnb[i0]);
            v.y = fmaf((hout[i1] - mu) * rs, lnw[i1], lnb[i1]);
            *reinterpret_cast<float2*>(op + t) = v;
        }
    }
}

// ---------------- launch ----------------------------------------------------
extern "C" void kernel_launch(void* const* d_in, const int* in_sizes, int n_in,
                              void* d_out, int out_size) {
    (void)in_sizes; (void)n_in; (void)out_size;
    const float* x      = (const float*)d_in[0];
    const float* mainp  = (const float*)d_in[1];
    const float* sidep  = (const float*)d_in[2];
    const float* conv_w = (const float*)d_in[3];
    const float* conv_b = (const float*)d_in[4];
    const float* bn_w   = (const float*)d_in[5];
    const float* bn_b   = (const float*)d_in[6];
    const float* bn_m   = (const float*)d_in[7];
    const float* bn_v   = (const float*)d_in[8];
    const float* m_Wih = (const float*)d_in[9];
    const float* m_Whh = (const float*)d_in[10];
    const float* m_bih = (const float*)d_in[11];
    const float* m_bhh = (const float*)d_in[12];
    const float* m_lnw = (const float*)d_in[13];
    const float* m_lnb = (const float*)d_in[14];
    const float* s_Wih = (const float*)d_in[15];
    const float* s_Whh = (const float*)d_in[16];
    const float* s_bih = (const float*)d_in[17];
    const float* s_bhh = (const float*)d_in[18];
    const float* s_lnw = (const float*)d_in[19];
    const float* s_lnb = (const float*)d_in[20];
    const float* a_Wih = (const float*)d_in[21];
    const float* a_Whh = (const float*)d_in[22];
    const float* a_bih = (const float*)d_in[23];
    const float* a_bhh = (const float*)d_in[24];
    const float* a_lnw = (const float*)d_in[25];
    const float* a_lnb = (const float*)d_in[26];

    float* out = (float*)d_out;
    float* out_xm  = out;                                   // [B,3,150]
    float* out_xs  = out + (size_t)BB * 3 * TMM;            // [B,3,400]
    float* out_xa  = out + (size_t)BB * 3 * (TMM + LL);     // [B,3,400]

    float* gm0; cudaGetSymbolAddress((void**)&gm0, g_m0);
    float* gs0; cudaGetSymbolAddress((void**)&gs0, g_s0);
    float* ga0; cudaGetSymbolAddress((void**)&ga0, g_a0);

    int nW = (BB + SEQW - 1) / SEQW;   // 205

    // 1. conv + bn + leakyrelu -> g_xa
    k_conv<<<(BB * LL + 255) / 256, 256>>>(x, conv_w, conv_b, bn_w, bn_b, bn_m, bn_v);
    // 2. xm_pre = xa @ main -> g_m0 [B,150,3] (float2 columns)
    k_mm_fwd_m<<<BB, 128>>>(mainp, gm0);
    // 3. xs_pre = xa @ side -> g_s0 [B,400,3] (float4 columns)
    k_mm_fwd_s<<<BB, 128>>>(sidep, gs0);
    // 4. LSTM+LN m & s -> out_xm, out_xs (transposed)
    k_lstm_ln<<<2 * nW, 32>>>(m_Wih, m_Whh, m_bih, m_bhh, m_lnw, m_lnb,
                              gm0, out_xm, TMM, BB, nW,
                              s_Wih, s_Whh, s_bih, s_bhh, s_lnw, s_lnb,
                              gs0, out_xs, LL, BB);
    // 5. xall_pre = xm @ main^T + xs @ side^T -> g_a0 (8-lane-group rows)
    k_mm_bwd<<<BB, 512>>>(out_xm, out_xs, mainp, sidep);
    // 6. LSTM+LN a -> out_xa
    k_lstm_ln<<<nW, 32>>>(a_Wih, a_Whh, a_bih, a_bhh, a_lnw, a_lnb,
                          ga0, out_xa, LL, BB, nW,
                          a_Wih, a_Whh, a_bih, a_bhh, a_lnw, a_lnb,
                          ga0, out_xa, LL, 0);
}

// round 14
// speedup vs baseline: 1.0393x; 1.0393x over previous
#include <cuda_runtime.h>
#include <cstdint>

#define BB 1024
#define LL 400
#define TMM 150
#define EPSF 1e-5f

// ---------------- scratch (device globals; no allocations allowed) ----------
__device__ float g_xa[(size_t)BB * 3 * LL];        // [B,3,400]
__device__ float g_m0[(size_t)BB * TMM * 3];       // [B,150,3]
__device__ float g_s0[(size_t)BB * LL * 3];        // [B,400,3]
__device__ float g_a0[(size_t)BB * LL * 3];        // [B,400,3]

// ---------------- helpers ---------------------------------------------------
__device__ __forceinline__ float tanh_(float x) {
    float y;
    asm("tanh.approx.f32 %0, %1;" : "=f"(y) : "f"(x));
    return y;
}
__device__ __forceinline__ float sigm_(float x) {
    return fmaf(0.5f, tanh_(0.5f * x), 0.5f);
}

// ---------------- conv1d + BN(eval) + LeakyReLU -----------------------------
__global__ void k_conv(const float* __restrict__ x,
                       const float* __restrict__ cw, const float* __restrict__ cb,
                       const float* __restrict__ bw, const float* __restrict__ bb,
                       const float* __restrict__ bm, const float* __restrict__ bv) {
    int idx = blockIdx.x * blockDim.x + threadIdx.x;
    if (idx >= BB * LL) return;
    int b = idx / LL, t = idx % LL;
    const float* xb = x + (size_t)b * 3 * LL;
    float in[3][3];
#pragma unroll
    for (int ci = 0; ci < 3; ci++)
#pragma unroll
        for (int k = 0; k < 3; k++) {
            int tt = t + k - 1;
            in[ci][k] = (tt >= 0 && tt < LL) ? xb[ci * LL + tt] : 0.0f;
        }
#pragma unroll
    for (int co = 0; co < 3; co++) {
        float acc = cb[co];
#pragma unroll
        for (int ci = 0; ci < 3; ci++)
#pragma unroll
            for (int k = 0; k < 3; k++)
                acc = fmaf(cw[(co * 3 + ci) * 3 + k], in[ci][k], acc);
        float sc = bw[co] * rsqrtf(bv[co] + EPSF);
        acc = fmaf(acc - bm[co], sc, bb[co]);
        acc = (acc >= 0.0f) ? acc : 0.01f * acc;
        g_xa[((size_t)b * 3 + co) * LL + t] = acc;
    }
}

// ---------------- forward matmul: out[b,t,c] = sum_k xa[b,c,k]*M[b,k,t] -----
__global__ void k_mm_fwd(const float* __restrict__ M, float* __restrict__ out, int T) {
    int b = blockIdx.x;
    __shared__ float sxa[3][LL];
    for (int i = threadIdx.x; i < 3 * LL; i += blockDim.x)
        sxa[i / LL][i % LL] = g_xa[(size_t)b * 3 * LL + i];
    __syncthreads();
    int t = threadIdx.x;
    if (t >= T) return;
    const float* Mb = M + (size_t)b * LL * T + t;
    float a0 = 0.f, a1 = 0.f, a2 = 0.f;
#pragma unroll 8
    for (int k = 0; k < LL; k++) {
        float mv = Mb[(size_t)k * T];
        a0 = fmaf(sxa[0][k], mv, a0);
        a1 = fmaf(sxa[1][k], mv, a1);
        a2 = fmaf(sxa[2][k], mv, a2);
    }
    float* o = out + ((size_t)b * T + t) * 3;
    o[0] = a0; o[1] = a1; o[2] = a2;
}

// ---------------- fused transpose matmul, 8-LANE-GROUP per row --------------
__global__ void k_mm_bwd(const float* __restrict__ xm,   // [B,3,150]
                         const float* __restrict__ xs,   // [B,3,400]
                         const float* __restrict__ M,    // [B,400,150]
                         const float* __restrict__ S) {  // [B,400,400]
    int b = blockIdx.x;
    __shared__ float sm_[3 * 152];
    __shared__ float ss_[3 * LL];
    const float* xmB = xm + (size_t)b * 3 * TMM;
    const float* xsB = xs + (size_t)b * 3 * LL;
    for (int i = threadIdx.x; i < 3 * TMM; i += blockDim.x)
        sm_[(i / TMM) * 152 + (i % TMM)] = xmB[i];
    for (int i = threadIdx.x; i < 3 * LL; i += blockDim.x)
        ss_[i] = xsB[i];
    __syncthreads();

    int warp = threadIdx.x >> 5, lane = threadIdx.x & 31;
    int grp = lane >> 3;          // 0..3  (row within warp-pass)
    int gl  = lane & 7;           // 0..7  (lane within group)
    int nWarps = blockDim.x >> 5;
    int rowsPerPass = nWarps * 4;

    for (int t0 = warp * 4 + grp; t0 < LL + 3; t0 += rowsPerPass) {
        bool valid = (t0 < LL);
        int t = valid ? t0 : (LL - 1);

        float a0 = 0.f, a1 = 0.f, a2 = 0.f;

        const float4* Sr = reinterpret_cast<const float4*>(S + ((size_t)b * LL + t) * LL);
        for (int k4 = gl; k4 < LL / 4; k4 += 8) {
            float4 v = Sr[k4];
            int k0 = 4 * k4;
            a0 = fmaf(ss_[k0], v.x, fmaf(ss_[k0 + 1], v.y, fmaf(ss_[k0 + 2], v.z, fmaf(ss_[k0 + 3], v.w, a0))));
            a1 = fmaf(ss_[LL + k0], v.x, fmaf(ss_[LL + k0 + 1], v.y, fmaf(ss_[LL + k0 + 2], v.z, fmaf(ss_[LL + k0 + 3], v.w, a1))));
            a2 = fmaf(ss_[2 * LL + k0], v.x, fmaf(ss_[2 * LL + k0 + 1], v.y, fmaf(ss_[2 * LL + k0 + 2], v.z, fmaf(ss_[2 * LL + k0 + 3], v.w, a2))));
        }

        const float2* Mr = reinterpret_cast<const float2*>(M + ((size_t)b * LL + t) * TMM);
        for (int j2 = gl; j2 < TMM / 2; j2 += 8) {
            float2 v = Mr[j2];
            int j0 = 2 * j2;
            a0 = fmaf(sm_[j0], v.x, fmaf(sm_[j0 + 1], v.y, a0));
            a1 = fmaf(sm_[152 + j0], v.x, fmaf(sm_[152 + j0 + 1], v.y, a1));
            a2 = fmaf(sm_[304 + j0], v.x, fmaf(sm_[304 + j0 + 1], v.y, a2));
        }

#pragma unroll
        for (int o = 4; o; o >>= 1) {
            a0 += __shfl_xor_sync(0xffffffffu, a0, o);
            a1 += __shfl_xor_sync(0xffffffffu, a1, o);
            a2 += __shfl_xor_sync(0xffffffffu, a2, o);
        }
        if (gl == 0 && valid) {
            float* o = g_a0 + ((size_t)b * LL + t) * 3;
            o[0] = a0; o[1] = a1; o[2] = a2;
        }
    }
}

// ---------------- fused 2-layer LSTM + LayerNorm, SMEM-resident -------------
// SOFTWARE-PIPELINED: layer 2 runs one step behind layer 1, so each body
// iteration evaluates two INDEPENDENT dependency chains {layer2(t-1),
// layer1(t)} that the scheduler interleaves. De-aliased sxin/shout buffers.
#define SEQW 5
__global__ void __launch_bounds__(32)
k_lstm_ln(const float* __restrict__ Wih0, const float* __restrict__ Whh0,
          const float* __restrict__ bih0, const float* __restrict__ bhh0,
          const float* __restrict__ lnw0, const float* __restrict__ lnb0,
          const float* __restrict__ in0, float* __restrict__ out0,
          int T0, int nB0, int nW0,
          const float* __restrict__ Wih1, const float* __restrict__ Whh1,
          const float* __restrict__ bih1, const float* __restrict__ bhh1,
          const float* __restrict__ lnw1, const float* __restrict__ lnb1,
          const float* __restrict__ in1, float* __restrict__ out1,
          int T1, int nB1) {
    __shared__ float sxin[SEQW * (3 * LL + 5)];   // 6025 words
    __shared__ float shout[SEQW * (3 * LL + 5)];  // 6025 words
    int warpId = blockIdx.x;
    int lane = threadIdx.x & 31;

    bool first = (warpId < nW0);
    const float* Wih = first ? Wih0 : Wih1;
    const float* Whh = first ? Whh0 : Whh1;
    const float* bih = first ? bih0 : bih1;
    const float* bhh = first ? bhh0 : bhh1;
    const float* lnw = first ? lnw0 : lnw1;
    const float* lnb = first ? lnb0 : lnb1;
    const float* inp = first ? in0 : in1;
    float* outp = first ? out0 : out1;
    int T  = first ? T0 : T1;
    int nB = first ? nB0 : nB1;
    int widx = first ? warpId : (warpId - nW0);

    int T3 = 3 * T;
    int stride = T3 + 5;                 // odd -> coprime with 32 banks
    int b0 = widx * SEQW;
    int nv = nB - b0; if (nv > SEQW) nv = SEQW;

    // ---- stage inputs into SMEM (coalesced) ----
    const float* src = inp + (size_t)b0 * T3;
    for (int s = 0; s < nv; s++)
        for (int i = lane; i < T3; i += 32)
            sxin[s * stride + i] = src[s * T3 + i];
    __syncwarp();

    // ---- lane mapping: 5 triples, lanes 15-31 shadow triple 4 ----
    int ln_ = (lane < 3 * SEQW) ? lane : (3 * SEQW - 1);
    int triple = ln_ / 3;
    int u = ln_ - triple * 3;
    int base = triple * 3;
    const float* xin = sxin + triple * stride;
    float* hout = shout + triple * stride;

    // ---- per-lane weights: gates (i,f,g,o) of unit u, layers 0/1 ----
    float wi1[4][3], wh1[4][3], b1[4], wi2[4][3], wh2[4][3], b2[4];
#pragma unroll
    for (int q = 0; q < 4; q++) {
        int gi = q * 3 + u;
#pragma unroll
        for (int v = 0; v < 3; v++) {
            wi1[q][v] = Wih[gi * 3 + v];
            wh1[q][v] = Whh[gi * 3 + v];
            wi2[q][v] = Wih[36 + gi * 3 + v];
            wh2[q][v] = Whh[36 + gi * 3 + v];
        }
        b1[q] = bih[gi] + bhh[gi];
        b2[q] = bih[12 + gi] + bhh[12 + gi];
    }

    float c1, c2 = 0.f;
    float h1a, h1b, h1c;
    float h2a = 0.f, h2b = 0.f, h2c = 0.f;
    float xc[4];

    // ---- prologue: layer1 step 0 (h1(-1)=0, c1(-1)=0) ----
    {
        float x0 = xin[0], x1 = xin[1], x2 = xin[2];
#pragma unroll
        for (int q = 0; q < 4; q++)
            xc[q] = fmaf(x0, wi1[q][0], fmaf(x1, wi1[q][1], fmaf(x2, wi1[q][2], b1[q])));
        float si = sigm_(xc[0]), tg = tanh_(xc[2]), so = sigm_(xc[3]);
        c1 = si * tg;
        float h1u = so * tanh_(c1);
        h1a = __shfl_sync(0xffffffffu, h1u, base);
        h1b = __shfl_sync(0xffffffffu, h1u, base + 1);
        h1c = __shfl_sync(0xffffffffu, h1u, base + 2);
        int t13 = (T > 1) ? 3 : 0;
        float y0 = xin[t13], y1 = xin[t13 + 1], y2 = xin[t13 + 2];
#pragma unroll
        for (int q = 0; q < 4; q++)
            xc[q] = fmaf(y0, wi1[q][0], fmaf(y1, wi1[q][1], fmaf(y2, wi1[q][2], b1[q])));
    }

    // ---- body t = 1..T-1: layer2(t-1) and layer1(t), independent chains ----
    for (int t = 1; t < T; t++) {
        int tn3 = ((t + 1 < T) ? (t + 1) : t) * 3;
        float fx0 = xin[tn3], fx1 = xin[tn3 + 1], fx2 = xin[tn3 + 2];

        // chain B: layer2 step t-1 (uses h1(t-1), h2(t-2))
        float g2[4];
#pragma unroll
        for (int q = 0; q < 4; q++)
            g2[q] = fmaf(h1a, wi2[q][0], fmaf(h1b, wi2[q][1], fmaf(h1c, wi2[q][2],
                    fmaf(h2a, wh2[q][0], fmaf(h2b, wh2[q][1], fmaf(h2c, wh2[q][2], b2[q]))))));

        // chain A: layer1 step t (uses h1(t-1), xc(t))
        float g1[4];
#pragma unroll
        for (int q = 0; q < 4; q++)
            g1[q] = fmaf(h1a, wh1[q][0], fmaf(h1b, wh1[q][1], fmaf(h1c, wh1[q][2], xc[q])));

        float si2 = sigm_(g2[0]), sf2 = sigm_(g2[1]), tg2 = tanh_(g2[2]), so2 = sigm_(g2[3]);
        float si1 = sigm_(g1[0]), sf1 = sigm_(g1[1]), tg1 = tanh_(g1[2]), so1 = sigm_(g1[3]);
        c2 = fmaf(sf2, c2, si2 * tg2);
        float h2u = so2 * tanh_(c2);
        c1 = fmaf(sf1, c1, si1 * tg1);
        float h1u = so1 * tanh_(c1);

        h1a = __shfl_sync(0xffffffffu, h1u, base);
        h1b = __shfl_sync(0xffffffffu, h1u, base + 1);
        h1c = __shfl_sync(0xffffffffu, h1u, base + 2);
        h2a = __shfl_sync(0xffffffffu, h2u, base);
        h2b = __shfl_sync(0xffffffffu, h2u, base + 1);
        h2c = __shfl_sync(0xffffffffu, h2u, base + 2);

        // xc(t+1), off both chains
#pragma unroll
        for (int q = 0; q < 4; q++)
            xc[q] = fmaf(fx0, wi1[q][0], fmaf(fx1, wi1[q][1], fmaf(fx2, wi1[q][2], b1[q])));

        hout[3 * (t - 1) + u] = h2u;
    }

    // ---- epilogue: layer2 step T-1 ----
    {
        float g2[4];
#pragma unroll
        for (int q = 0; q < 4; q++)
            g2[q] = fmaf(h1a, wi2[q][0], fmaf(h1b, wi2[q][1], fmaf(h1c, wi2[q][2],
                    fmaf(h2a, wh2[q][0], fmaf(h2b, wh2[q][1], fmaf(h2c, wh2[q][2], b2[q]))))));
        float si2 = sigm_(g2[0]), sf2 = sigm_(g2[1]), tg2 = tanh_(g2[2]), so2 = sigm_(g2[3]);
        c2 = fmaf(sf2, c2, si2 * tg2);
        float h2u = so2 * tanh_(c2);
        hout[3 * (T - 1) + u] = h2u;
    }
    __syncwarp();

    // ---- LayerNorm over (T,3) per sequence, write transposed [3,T] ----
    float s1 = 0.f, s2 = 0.f;
    for (int t = 0; t < T; t++) {
        float v = hout[3 * t + u];
        s1 += v;
        s2 = fmaf(v, v, s2);
    }
    float sa = __shfl_sync(0xffffffffu, s1, base) +
               __shfl_sync(0xffffffffu, s1, base + 1) +
               __shfl_sync(0xffffffffu, s1, base + 2);
    float sq = __shfl_sync(0xffffffffu, s2, base) +
               __shfl_sync(0xffffffffu, s2, base + 1) +
               __shfl_sync(0xffffffffu, s2, base + 2);
    float invn = 1.0f / (float)T3;
    float mu = sa * invn;
    float var = sq * invn - mu * mu;
    float rs = rsqrtf(var + EPSF);

    int b = b0 + triple;
    bool ok = (lane < 3 * SEQW) && (b < nB);
    if (ok) {
        float* op = outp + (size_t)b * T3 + u * T;   // [B,3,T], row u
        for (int t2 = 0; t2 < T / 2; t2++) {
            int t = 2 * t2;
            int i0 = 3 * t + u, i1 = 3 * t + 3 + u;
            float2 v;
            v.x = fmaf((hout[i0] - mu) * rs, lnw[i0], lnb[i0]);
            v.y = fmaf((hout[i1] - mu) * rs, lnw[i1], lnb[i1]);
            *reinterpret_cast<float2*>(op + t) = v;
        }
    }
}

// ---------------- launch ----------------------------------------------------
extern "C" void kernel_launch(void* const* d_in, const int* in_sizes, int n_in,
                              void* d_out, int out_size) {
    (void)in_sizes; (void)n_in; (void)out_size;
    const float* x      = (const float*)d_in[0];
    const float* mainp  = (const float*)d_in[1];
    const float* sidep  = (const float*)d_in[2];
    const float* conv_w = (const float*)d_in[3];
    const float* conv_b = (const float*)d_in[4];
    const float* bn_w   = (const float*)d_in[5];
    const float* bn_b   = (const float*)d_in[6];
    const float* bn_m   = (const float*)d_in[7];
    const float* bn_v   = (const float*)d_in[8];
    const float* m_Wih = (const float*)d_in[9];
    const float* m_Whh = (const float*)d_in[10];
    const float* m_bih = (const float*)d_in[11];
    const float* m_bhh = (const float*)d_in[12];
    const float* m_lnw = (const float*)d_in[13];
    const float* m_lnb = (const float*)d_in[14];
    const float* s_Wih = (const float*)d_in[15];
    const float* s_Whh = (const float*)d_in[16];
    const float* s_bih = (const float*)d_in[17];
    const float* s_bhh = (const float*)d_in[18];
    const float* s_lnw = (const float*)d_in[19];
    const float* s_lnb = (const float*)d_in[20];
    const float* a_Wih = (const float*)d_in[21];
    const float* a_Whh = (const float*)d_in[22];
    const float* a_bih = (const float*)d_in[23];
    const float* a_bhh = (const float*)d_in[24];
    const float* a_lnw = (const float*)d_in[25];
    const float* a_lnb = (const float*)d_in[26];

    float* out = (float*)d_out;
    float* out_xm  = out;                                   // [B,3,150]
    float* out_xs  = out + (size_t)BB * 3 * TMM;            // [B,3,400]
    float* out_xa  = out + (size_t)BB * 3 * (TMM + LL);     // [B,3,400]

    float* gm0; cudaGetSymbolAddress((void**)&gm0, g_m0);
    float* gs0; cudaGetSymbolAddress((void**)&gs0, g_s0);
    float* ga0; cudaGetSymbolAddress((void**)&ga0, g_a0);

    int nW = (BB + SEQW - 1) / SEQW;   // 205

    // 1. conv + bn + leakyrelu -> g_xa
    k_conv<<<(BB * LL + 255) / 256, 256>>>(x, conv_w, conv_b, bn_w, bn_b, bn_m, bn_v);
    // 2. xm_pre = xa @ main -> g_m0 [B,150,3]
    k_mm_fwd<<<BB, 160>>>(mainp, gm0, TMM);
    // 3. xs_pre = xa @ side -> g_s0 [B,400,3]
    k_mm_fwd<<<BB, 416>>>(sidep, gs0, LL);
    // 4. LSTM+LN m & s -> out_xm, out_xs (transposed)
    k_lstm_ln<<<2 * nW, 32>>>(m_Wih, m_Whh, m_bih, m_bhh, m_lnw, m_lnb,
                              gm0, out_xm, TMM, BB, nW,
                              s_Wih, s_Whh, s_bih, s_bhh, s_lnw, s_lnb,
                              gs0, out_xs, LL, BB);
    // 5. xall_pre = xm @ main^T + xs @ side^T -> g_a0 (8-lane-group rows)
    k_mm_bwd<<<BB, 512>>>(out_xm, out_xs, mainp, sidep);
    // 6. LSTM+LN a -> out_xa
    k_lstm_ln<<<nW, 32>>>(a_Wih, a_Whh, a_bih, a_bhh, a_lnw, a_lnb,
                          ga0, out_xa, LL, BB, nW,
                          a_Wih, a_Whh, a_bih, a_bhh, a_lnw, a_lnb,
                          ga0, out_xa, LL, 0);
}